// round 15
// baseline (speedup 1.0000x reference)
#include <cuda_runtime.h>
#include <cuda_fp16.h>
#include <math.h>

#define BB   32
#define LQ   512
#define DD   384
#define FF   384
#define MROWS (BB*LQ)      // 16384
#define KDIM  (DD*3)       // 1152 halves
#define LN_EPS 1e-5f
#define STAGES 3
#define RSH 48             // halves per smem row (96 B) -- proven conflict-free
#define A_ROWS 64
#define B_ROWS 384
#define STG_A (A_ROWS*RSH)             // 3072 halves
#define STG_B (B_ROWS*RSH)             // 18432 halves
#define SMEMB (STAGES*(STG_A+STG_B)*2) // 129024 bytes
#define GEMM_BLOCKS (MROWS/64)         // 256
#define NPX2 (MROWS*DD/2/256)          // 12288
#define NWR (FF*2)                     // 768

// Scratch (no allocations allowed).
__device__ __half g_buf2h[(size_t)MROWS * FF];   // conv1 out (fp16, permuted)
__device__ __half g_xph [(size_t)MROWS * DD];
__device__ __half g_w1rh[(size_t)FF * KDIM];
__device__ __half g_w2rh[(size_t)FF * KDIM];
__device__ int    g_fidx[BB * 8192];

// Half-pair permutation within each 16-half block.
__device__ __forceinline__ int perm16h(int j)
{
    const int p = j >> 1;
    const int pos = (p < 4) ? 2 * p : 2 * (p - 4) + 1;
    return pos * 2 + (j & 1);
}

// ---------------------------------------------------------------------------
// Fused prep (R13-proven): x fp32->fp16 permuted ; W reorder ; frame indices.
// ---------------------------------------------------------------------------
__global__ __launch_bounds__(256) void prep_all_kernel(
    const float* __restrict__ x, __half* __restrict__ xp,
    const float* __restrict__ W1, __half* __restrict__ Wr1,
    const float* __restrict__ W2, __half* __restrict__ Wr2,
    const int* __restrict__ target, int M)
{
    const int bidx = blockIdx.x;
    const int t = threadIdx.x;

    if (bidx < NPX2) {
        const int idx2 = bidx * 256 + t;
        const int row  = idx2 / 192;
        const int pc   = idx2 - row * 192;
        const int blk  = pc >> 3, p = pc & 7;
        const int pos  = (p < 4) ? 2 * p : 2 * (p - 4) + 1;
        const float2 v = *(const float2*)&x[(size_t)row * DD + (blk << 4) + p * 2];
        *(__half2*)&xp[(size_t)row * DD + (blk << 4) + pos * 2] =
            __floats2half2_rn(v.x, v.y);
    } else if (bidx < NPX2 + NWR) {
        const int r2 = bidx - NPX2;
        const float* W  = (r2 >= FF) ? W2 : W1;
        __half*     Wr = (r2 >= FF) ? Wr2 : Wr1;
        const int f = (r2 >= FF) ? r2 - FF : r2;
        for (int i = t; i < KDIM; i += 256) {
            const int kseg = i / DD;
            const int r    = i - kseg * DD;
            const int blk  = r >> 4, j = r & 15;
            const int dst  = kseg * DD + (blk << 4) + perm16h(j);
            Wr[(size_t)f * KDIM + dst] =
                __float2half_rn(W[(size_t)f * KDIM + (blk * 16 + j) * 3 + kseg]);
        }
    } else {
        __shared__ int s[512];
        const int fb  = bidx - (NPX2 + NWR);
        const int bpB = M >> 8;
        const int b   = fb / bpB;
        const int fr0 = (fb - b * bpB) * 256;
        s[t]       = target[b * LQ + t];
        s[t + 256] = target[b * LQ + t + 256];
        __syncthreads();
        for (int off = 1; off < 512; off <<= 1) {
            const int v0 = (t >= off) ? s[t - off] : 0;
            const int v1 = s[t + 256 - off];
            __syncthreads();
            s[t] += v0;
            s[t + 256] += v1;
            __syncthreads();
        }
        const int fr = fr0 + t;
        const int total = s[511];
        int idx = -1;
        if (fr < total) {
            int lo = 0, hi = LQ;
            while (lo < hi) {
                const int mid = (lo + hi) >> 1;
                if (s[mid] <= fr) lo = mid + 1; else hi = mid;
            }
            idx = min(lo, LQ - 1);
        }
        g_fidx[b * M + fr] = idx;
    }
}

__device__ __forceinline__ void mma_f16(float c[4], unsigned a0, unsigned a1,
                                        unsigned a2, unsigned a3,
                                        unsigned b0, unsigned b1)
{
    asm volatile(
        "mma.sync.aligned.m16n8k16.row.col.f32.f16.f16.f32 "
        "{%0,%1,%2,%3}, {%4,%5,%6,%7}, {%8,%9}, {%0,%1,%2,%3};"
        : "+f"(c[0]), "+f"(c[1]), "+f"(c[2]), "+f"(c[3])
        : "r"(a0), "r"(a1), "r"(a2), "r"(a3), "r"(b0), "r"(b1));
}

__device__ __forceinline__ void cp16(unsigned dst, const void* src, bool p)
{
    const int sz = p ? 16 : 0;
    asm volatile("cp.async.cg.shared.global [%0], [%1], 16, %2;\n"
                 :: "r"(dst), "l"(src), "r"(sz));
}

// ---------------------------------------------------------------------------
// Fused conv(+LN) + expand. Conv blocks [0,256): CTA = 64(M) x 384(N) full
// stripe, 512 thr, 16 warps 2m x 8n (warp 32x48), BK=32, 3-stage cp.async.
// Epilogue: in-CTA LayerNorm (smem-atomic row stats). mode 0 -> fp16 permuted
// OutH; mode 1 -> LN+ReLU dot lin_w -> dur. Blocks >= 256: expand (16-frame
// groups, 512 thr) via g_fidx.
// ---------------------------------------------------------------------------
__global__ __launch_bounds__(512) void conv_expand_kernel(
    const __half* __restrict__ Asrc, const __half* __restrict__ Wr,
    const float* __restrict__ bias, const float* __restrict__ gam,
    const float* __restrict__ bet, const float* __restrict__ lw,
    const float* __restrict__ lb, __half* __restrict__ OutH,
    float* __restrict__ dur,
    const float* __restrict__ X, float* __restrict__ out,
    int M, int exp_base, int mode)
{
    if (blockIdx.x >= GEMM_BLOCKS) {
        // ---------------- expand: 16 frames = 1536 float4 over 512 thr ------
        const int g = blockIdx.x - GEMM_BLOCKS + exp_base;
        if (g >= BB * (M >> 4)) return;
        const int gpb = M >> 4;
        const int b   = g / gpb;
        const int fg  = g - b * gpb;
        const int* fi = g_fidx + b * M + fg * 16;
        float4* obase = (float4*)(out + (size_t)b * M * DD) + (size_t)fg * 1536;
        #pragma unroll
        for (int i = 0; i < 3; ++i) {
            const int idx  = i * 512 + threadIdx.x;
            const int fr16 = idx / 96;
            const int lane = idx - fr16 * 96;
            const int sidx = __ldg(&fi[fr16]);
            if (sidx < 0) {
                __stcs(&obase[idx], make_float4(0.f, 0.f, 0.f, 0.f));
            } else {
                const float4* src = (const float4*)(X + ((size_t)b * LQ + sidx) * DD);
                __stcs(&obase[idx], __ldg(&src[lane]));
            }
        }
        return;
    }

    // ---------------- conv ----------------
    extern __shared__ __half smh[];
    const int m0 = blockIdx.x * 64;
    const int t  = threadIdx.x;
    const int lane = t & 31, grp = lane >> 2, tig = lane & 3;
    const int warp = t >> 5;                 // 0..15
    const int m_base = (warp & 1) * 32;
    const int nb     = (warp >> 1) * 48;

    const unsigned smbase = (unsigned)__cvta_generic_to_shared(&smh[0]);
    const unsigned STB_A = STG_A * 2;        // 6144 B
    const unsigned STB_B = STG_B * 2;        // 36864 B
    const unsigned BOFF  = STAGES * STB_A;   // 18432 B

    float acc[2][6][4] = {};

    // loader: 1792 16B-chunks per stage (A 256 + B 1536); 4 reps of 512
    auto load_tile = [&](int it, int st) {
        const int kk0  = it * 32;
        const int kseg = (kk0 >= 384) + (kk0 >= 768);
        const int off  = kk0 - kseg * DD;
        #pragma unroll
        for (int rep = 0; rep < 4; ++rep) {
            const int id = t + rep * 512;
            if (id < 256) {                          // A chunk
                const int row = id >> 2, c = id & 3;
                const int m = m0 + row;
                const int l = (m & 511) + kseg - 1;
                const bool v = (l >= 0) & (l < LQ);
                const __half* src = Asrc
                    + ((size_t)((m >> 9) << 9) + (v ? l : 0)) * DD + off + c * 8;
                cp16(smbase + st * STB_A + row * 96 + c * 16, src, v);
            } else if (id < 1792) {                  // B chunk
                const int id2 = id - 256;
                const int row = id2 >> 2, c = id2 & 3;
                const __half* src = Wr + (size_t)row * KDIM + kseg * DD + off + c * 8;
                cp16(smbase + BOFF + st * STB_B + row * 96 + c * 16, src, true);
            }
        }
    };

    load_tile(0, 0);
    asm volatile("cp.async.commit_group;");
    load_tile(1, 1);
    asm volatile("cp.async.commit_group;");
    asm volatile("cp.async.wait_group 1;");
    __syncthreads();

    const int NIT = KDIM / 32;   // 36
    int st_next = 2, buf = 0;
    for (int it = 0; it < NIT; ++it) {
        if (it + 2 < NIT) load_tile(it + 2, st_next);
        asm volatile("cp.async.commit_group;");
        if (++st_next == STAGES) st_next = 0;

        const __half* Ab = smh + buf * STG_A;
        const __half* Bb = smh + STAGES * STG_A + buf * STG_B;
        #pragma unroll
        for (int ks = 0; ks < 2; ++ks) {
            const int pch = ks * 16 + tig * 4;
            uint2 bf[6];
            #pragma unroll
            for (int nt = 0; nt < 6; ++nt)
                bf[nt] = *(const uint2*)&Bb[(nb + nt * 8 + grp) * RSH + pch];
            #pragma unroll
            for (int mt = 0; mt < 2; ++mt) {
                const int ar = m_base + mt * 16 + grp;
                const uint2 ua = *(const uint2*)&Ab[ar * RSH + pch];
                const uint2 ub = *(const uint2*)&Ab[(ar + 8) * RSH + pch];
                #pragma unroll
                for (int nt = 0; nt < 6; ++nt)
                    mma_f16(acc[mt][nt], ua.x, ub.x, ua.y, ub.y,
                            bf[nt].x, bf[nt].y);
            }
        }
        if (++buf == STAGES) buf = 0;

        asm volatile("cp.async.wait_group 1;");
        __syncthreads();
    }
    asm volatile("cp.async.wait_group 0;");
    __syncthreads();

    // ---------------- epilogue: fused LayerNorm ----------------
    float* ep = (float*)smh;   // bias[384] gam[384] bet[384] lw[384] stats[128] dur[64]
    for (int i = t; i < 384; i += 512) {
        ep[i]          = bias[i];
        ep[384 + i]    = gam[i];
        ep[768 + i]    = bet[i];
        ep[1152 + i]   = lw[i];
    }
    for (int i = t; i < 192; i += 512) ep[1536 + i] = 0.f;
    __syncthreads();

    // per-thread partial (sum, sumsq) for its two row-groups
    #pragma unroll
    for (int mt = 0; mt < 2; ++mt) {
        float s0 = 0.f, q0 = 0.f, s1 = 0.f, q1 = 0.f;
        #pragma unroll
        for (int nt = 0; nt < 6; ++nt) {
            const int fc = nb + nt * 8 + 2 * tig;
            const float b0v = ep[fc], b1v = ep[fc + 1];
            const float v0 = acc[mt][nt][0] + b0v, v1 = acc[mt][nt][1] + b1v;
            const float v2 = acc[mt][nt][2] + b0v, v3 = acc[mt][nt][3] + b1v;
            s0 += v0 + v1; q0 += v0 * v0 + v1 * v1;
            s1 += v2 + v3; q1 += v2 * v2 + v3 * v3;
        }
        s0 += __shfl_down_sync(0xffffffffu, s0, 2); s0 += __shfl_down_sync(0xffffffffu, s0, 1);
        q0 += __shfl_down_sync(0xffffffffu, q0, 2); q0 += __shfl_down_sync(0xffffffffu, q0, 1);
        s1 += __shfl_down_sync(0xffffffffu, s1, 2); s1 += __shfl_down_sync(0xffffffffu, s1, 1);
        q1 += __shfl_down_sync(0xffffffffu, q1, 2); q1 += __shfl_down_sync(0xffffffffu, q1, 1);
        if (tig == 0) {
            const int r0 = m_base + mt * 16 + grp;
            atomicAdd(&ep[1536 + 2 * r0], s0);
            atomicAdd(&ep[1536 + 2 * r0 + 1], q0);
            atomicAdd(&ep[1536 + 2 * (r0 + 8)], s1);
            atomicAdd(&ep[1536 + 2 * (r0 + 8) + 1], q1);
        }
    }
    __syncthreads();

    if (mode == 0) {
        #pragma unroll
        for (int mt = 0; mt < 2; ++mt) {
            const int r0 = m_base + mt * 16 + grp;
            #pragma unroll
            for (int h = 0; h < 2; ++h) {
                const int r = r0 + h * 8;
                const float mu = ep[1536 + 2 * r] * (1.f / FF);
                const float rs = rsqrtf(ep[1536 + 2 * r + 1] * (1.f / FF) - mu * mu + LN_EPS);
                __half* op = OutH + (size_t)(m0 + r) * FF;
                #pragma unroll
                for (int nt = 0; nt < 6; ++nt) {
                    const int fc = nb + nt * 8 + 2 * tig;
                    const float v0 = acc[mt][nt][2 * h]     + ep[fc];
                    const float v1 = acc[mt][nt][2 * h + 1] + ep[fc + 1];
                    const float h0 = fmaxf(fmaf((v0 - mu) * rs, ep[384 + fc], ep[768 + fc]), 0.f);
                    const float h1 = fmaxf(fmaf((v1 - mu) * rs, ep[384 + fc + 1], ep[768 + fc + 1]), 0.f);
                    const int dcol = (fc & ~15) + perm16h(fc & 15);
                    *(__half2*)&op[dcol] = __floats2half2_rn(h0, h1);
                }
            }
        }
    } else {
        #pragma unroll
        for (int mt = 0; mt < 2; ++mt) {
            const int r0 = m_base + mt * 16 + grp;
            float d0 = 0.f, d1 = 0.f;
            #pragma unroll
            for (int h = 0; h < 2; ++h) {
                const int r = r0 + h * 8;
                const float mu = ep[1536 + 2 * r] * (1.f / FF);
                const float rs = rsqrtf(ep[1536 + 2 * r + 1] * (1.f / FF) - mu * mu + LN_EPS);
                float d = 0.f;
                #pragma unroll
                for (int nt = 0; nt < 6; ++nt) {
                    const int fc = nb + nt * 8 + 2 * tig;
                    const float v0 = acc[mt][nt][2 * h]     + ep[fc];
                    const float v1 = acc[mt][nt][2 * h + 1] + ep[fc + 1];
                    const float h0 = fmaxf(fmaf((v0 - mu) * rs, ep[384 + fc], ep[768 + fc]), 0.f);
                    const float h1 = fmaxf(fmaf((v1 - mu) * rs, ep[384 + fc + 1], ep[768 + fc + 1]), 0.f);
                    d += h0 * ep[1152 + fc] + h1 * ep[1152 + fc + 1];
                }
                if (h == 0) d0 = d; else d1 = d;
            }
            d0 += __shfl_down_sync(0xffffffffu, d0, 2); d0 += __shfl_down_sync(0xffffffffu, d0, 1);
            d1 += __shfl_down_sync(0xffffffffu, d1, 2); d1 += __shfl_down_sync(0xffffffffu, d1, 1);
            if (tig == 0) {
                atomicAdd(&ep[1664 + r0], d0);
                atomicAdd(&ep[1664 + r0 + 8], d1);
            }
        }
        __syncthreads();
        if (t < 64)
            dur[m0 + t] = fmaxf(ep[1664 + t] + __ldg(&lb[0]), 0.f);
    }
}

// ---------------------------------------------------------------------------
extern "C" void kernel_launch(void* const* d_in, const int* in_sizes, int n_in,
                              void* d_out, int out_size)
{
    const float* x     = (const float*)d_in[0];
    const float* c1_w  = (const float*)d_in[1];
    const float* c1_b  = (const float*)d_in[2];
    const float* ln1_g = (const float*)d_in[3];
    const float* ln1_b = (const float*)d_in[4];
    const float* c2_w  = (const float*)d_in[5];
    const float* c2_b  = (const float*)d_in[6];
    const float* ln2_g = (const float*)d_in[7];
    const float* ln2_b = (const float*)d_in[8];
    const float* lin_w = (const float*)d_in[9];
    const float* lin_b = (const float*)d_in[10];
    const int*   target= (const int*)d_in[11];

    const int M = (out_size - BB * LQ) / (BB * DD);

    __half* buf2h; cudaGetSymbolAddress((void**)&buf2h, g_buf2h);
    __half* xph;   cudaGetSymbolAddress((void**)&xph,   g_xph);
    __half* w1rh;  cudaGetSymbolAddress((void**)&w1rh,  g_w1rh);
    __half* w2rh;  cudaGetSymbolAddress((void**)&w2rh,  g_w2rh);

    float* out_expand = (float*)d_out;
    float* out_dur    = (float*)d_out + (size_t)BB * M * DD;

    cudaFuncSetAttribute(conv_expand_kernel,
                         cudaFuncAttributeMaxDynamicSharedMemorySize, SMEMB);

    const int nfi       = BB * (M >> 8);
    const int exp_total = BB * (M >> 4);   // 8192 (16-frame groups)
    const int exp_half  = exp_total / 2;

    prep_all_kernel<<<NPX2 + NWR + nfi, 256>>>(x, xph, c1_w, w1rh, c2_w, w2rh,
                                               target, M);
    conv_expand_kernel<<<GEMM_BLOCKS + exp_half, 512, SMEMB>>>(
        xph, w1rh, c1_b, ln1_g, ln1_b, lin_w, lin_b, buf2h, out_dur,
        x, out_expand, M, 0, 0);
    conv_expand_kernel<<<GEMM_BLOCKS + (exp_total - exp_half), 512, SMEMB>>>(
        buf2h, w2rh, c2_b, ln2_g, ln2_b, lin_w, lin_b, buf2h, out_dur,
        x, out_expand, M, exp_half, 1);
}

// round 16
// speedup vs baseline: 1.2413x; 1.2413x over previous
#include <cuda_runtime.h>
#include <cuda_fp16.h>
#include <math.h>

#define BB   32
#define LQ   512
#define DD   384
#define FF   384
#define MROWS (BB*LQ)      // 16384
#define KDIM  (DD*3)       // 1152 halves
#define LN_EPS 1e-5f
#define STAGES 3
#define RSH 48             // smem row stride in halves (96 B)
#define GEMM_BLOCKS ((MROWS/64)*(FF/64))    // 1536
#define NPX8 (MROWS*DD/8/256)               // 3072 (8 halves per thread)
#define NWR (FF*2)                          // 768

// Scratch (no allocations allowed).
__device__ float  g_buf1[(size_t)MROWS * FF];
__device__ __half g_buf2h[(size_t)MROWS * FF];
__device__ __half g_xph [(size_t)MROWS * DD];
__device__ __half g_w1rh[(size_t)FF * KDIM];
__device__ __half g_w2rh[(size_t)FF * KDIM];
__device__ int    g_fidx[BB * 8192];        // frame -> source phoneme (-1 = pad)

// Half-pair permutation within each 16-half block.
__device__ __forceinline__ int perm16h(int j)
{
    const int p = j >> 1;
    const int pos = (p < 4) ? 2 * p : 2 * (p - 4) + 1;
    return pos * 2 + (j & 1);
}

// ---------------------------------------------------------------------------
// Fused prep: [0,NPX8) x fp32->fp16, 8 halves (one half of a 16-block) per
// thread ; [NPX8,NPX8+NWR) W reorder ; then frame-index blocks.
// ---------------------------------------------------------------------------
__global__ __launch_bounds__(256) void prep_all_kernel(
    const float* __restrict__ x, __half* __restrict__ xp,
    const float* __restrict__ W1, __half* __restrict__ Wr1,
    const float* __restrict__ W2, __half* __restrict__ Wr2,
    const int* __restrict__ target, int M)
{
    const int bidx = blockIdx.x;
    const int t = threadIdx.x;

    if (bidx < NPX8) {
        const int i   = bidx * 256 + t;       // 8-half group id
        const int b16 = i >> 1;               // 16-half block
        const int h   = i & 1;                // which half of the block
        const size_t sbase = (size_t)b16 * 16 + h * 8;
        const float4 v0 = *(const float4*)&x[sbase];
        const float4 v1 = *(const float4*)&x[sbase + 4];
        // pairs p = h*4+q -> dest half offset (h?2:0) + q*4  within the block
        __half* d = xp + (size_t)b16 * 16 + (h ? 2 : 0);
        *(__half2*)&d[0]  = __floats2half2_rn(v0.x, v0.y);
        *(__half2*)&d[4]  = __floats2half2_rn(v0.z, v0.w);
        *(__half2*)&d[8]  = __floats2half2_rn(v1.x, v1.y);
        *(__half2*)&d[12] = __floats2half2_rn(v1.z, v1.w);
    } else if (bidx < NPX8 + NWR) {
        const int r2 = bidx - NPX8;
        const float* W  = (r2 >= FF) ? W2 : W1;
        __half*     Wr = (r2 >= FF) ? Wr2 : Wr1;
        const int f = (r2 >= FF) ? r2 - FF : r2;
        for (int i = t; i < KDIM; i += 256) {
            const int kseg = i / DD;
            const int r    = i - kseg * DD;
            const int blk  = r >> 4, j = r & 15;
            const int dst  = kseg * DD + (blk << 4) + perm16h(j);
            Wr[(size_t)f * KDIM + dst] =
                __float2half_rn(W[(size_t)f * KDIM + (blk * 16 + j) * 3 + kseg]);
        }
    } else {
        __shared__ int s[512];
        const int fb  = bidx - (NPX8 + NWR);
        const int bpB = M >> 8;
        const int b   = fb / bpB;
        const int fr0 = (fb - b * bpB) * 256;
        s[t]       = target[b * LQ + t];
        s[t + 256] = target[b * LQ + t + 256];
        __syncthreads();
        for (int off = 1; off < 512; off <<= 1) {
            const int v0 = (t >= off) ? s[t - off] : 0;
            const int v1 = s[t + 256 - off];
            __syncthreads();
            s[t] += v0;
            s[t + 256] += v1;
            __syncthreads();
        }
        const int fr = fr0 + t;
        const int total = s[511];
        int idx = -1;
        if (fr < total) {
            int lo = 0, hi = LQ;
            while (lo < hi) {
                const int mid = (lo + hi) >> 1;
                if (s[mid] <= fr) lo = mid + 1; else hi = mid;
            }
            idx = min(lo, LQ - 1);
        }
        g_fidx[b * M + fr] = idx;
    }
}

__device__ __forceinline__ void mma_f16(float c[4], unsigned a0, unsigned a1,
                                        unsigned a2, unsigned a3,
                                        unsigned b0, unsigned b1)
{
    asm volatile(
        "mma.sync.aligned.m16n8k16.row.col.f32.f16.f16.f32 "
        "{%0,%1,%2,%3}, {%4,%5,%6,%7}, {%8,%9}, {%0,%1,%2,%3};"
        : "+f"(c[0]), "+f"(c[1]), "+f"(c[2]), "+f"(c[3])
        : "r"(a0), "r"(a1), "r"(a2), "r"(a3), "r"(b0), "r"(b1));
}

__device__ __forceinline__ void cp16(unsigned dst, const void* src, bool p)
{
    const int sz = p ? 16 : 0;
    asm volatile("cp.async.cg.shared.global [%0], [%1], 16, %2;\n"
                 :: "r"(dst), "l"(src), "r"(sz));
}

// ---------------------------------------------------------------------------
// Conv fp16 mma (R12-proven): CTA 64x64, BK=32, 128 thr, 4 warps 2x2,
// 3-stage cp.async, 6 CTAs/SM. Grid order f-major within m so concurrent
// CTAs share A rows in L2. Blocks >= GEMM_BLOCKS: expand via g_fidx.
// ---------------------------------------------------------------------------
__global__ __launch_bounds__(128, 6) void conv_expand_kernel(
    const __half* __restrict__ Asrc, const __half* __restrict__ Wr,
    const float* __restrict__ bias, float* __restrict__ Y,
    const float* __restrict__ X, float* __restrict__ out,
    int M, int exp_base)
{
    if (blockIdx.x >= GEMM_BLOCKS) {
        const int g   = blockIdx.x - GEMM_BLOCKS + exp_base;
        const int gpb = M >> 3;
        const int b   = g / gpb;
        const int fg  = g - b * gpb;
        const int* fi = g_fidx + b * M + fg * 8;
        float4* obase = (float4*)(out + (size_t)b * M * DD) + (size_t)fg * 768;
        #pragma unroll
        for (int i = 0; i < 6; ++i) {
            const int idx  = i * 128 + threadIdx.x;
            const int fr8  = idx / 96;
            const int lane = idx - fr8 * 96;
            const int sidx = __ldg(&fi[fr8]);
            if (sidx < 0) {
                __stcs(&obase[idx], make_float4(0.f, 0.f, 0.f, 0.f));
            } else {
                const float4* src = (const float4*)(X + ((size_t)b * LQ + sidx) * DD);
                __stcs(&obase[idx], __ldg(&src[lane]));
            }
        }
        return;
    }

    // ---------------- conv ----------------
    extern __shared__ __half smh[];
    __half* As = smh;                          // [STAGES][64][RSH]
    __half* Bs = smh + STAGES * 64 * RSH;      // [STAGES][64][RSH]

    const int f0 = (blockIdx.x % 6) * 64;      // f-major: concurrent CTAs share A
    const int m0 = (blockIdx.x / 6) * 64;
    const int t  = threadIdx.x;
    const int lane = t & 31, grp = lane >> 2, tig = lane & 3;
    const int warp = t >> 5;
    const int m_base = (warp & 1) * 32;
    const int n_base = (warp >> 1) * 32;

    const int lrow = t >> 2;            // 0..31
    const int c    = t & 3;

    int bA[2], lA[2];
    #pragma unroll
    for (int rr = 0; rr < 2; ++rr) {
        const int m = m0 + lrow + rr * 32;
        bA[rr] = m >> 9;
        lA[rr] = m & 511;
    }

    const unsigned aAd0 = (unsigned)__cvta_generic_to_shared(&As[lrow * RSH + c * 8]);
    const unsigned bAd0 = (unsigned)__cvta_generic_to_shared(&Bs[lrow * RSH + c * 8]);
    const unsigned STB   = 64 * RSH * 2;    // 6144
    const unsigned ROW32 = 32 * RSH * 2;    // 3072

    const __half* wr0 = Wr + (size_t)(f0 + lrow) * KDIM + c * 8;
    const __half* wr1 = Wr + (size_t)(f0 + lrow + 32) * KDIM + c * 8;

    float acc[2][4][4] = {};

    auto load_tile = [&](int it, int st) {
        const int kk0  = it * 32;
        const int kseg = (kk0 >= 384) + (kk0 >= 768);
        const int off  = kk0 - kseg * DD + c * 8;
        #pragma unroll
        for (int rr = 0; rr < 2; ++rr) {
            const int l2 = lA[rr] + kseg - 1;
            const bool v = (l2 >= 0) & (l2 < LQ);
            const __half* sa = Asrc + ((size_t)(bA[rr] << 9) + (v ? l2 : 0)) * DD + off;
            cp16(aAd0 + st * STB + rr * ROW32, sa, v);
        }
        cp16(bAd0 + st * STB,         wr0 + kk0, true);
        cp16(bAd0 + st * STB + ROW32, wr1 + kk0, true);
    };

    load_tile(0, 0);
    asm volatile("cp.async.commit_group;");
    load_tile(1, 1);
    asm volatile("cp.async.commit_group;");
    asm volatile("cp.async.wait_group 1;");
    __syncthreads();

    const int NIT = KDIM / 32;   // 36
    int st_next = 2, buf = 0;
    for (int it = 0; it < NIT; ++it) {
        if (it + 2 < NIT) load_tile(it + 2, st_next);
        asm volatile("cp.async.commit_group;");
        if (++st_next == STAGES) st_next = 0;

        const __half* Ab = As + buf * 64 * RSH;
        const __half* Bb = Bs + buf * 64 * RSH;
        #pragma unroll
        for (int ks = 0; ks < 2; ++ks) {
            const int pch = ks * 16 + tig * 4;
            uint2 bf[4];
            #pragma unroll
            for (int nt = 0; nt < 4; ++nt)
                bf[nt] = *(const uint2*)&Bb[(n_base + nt * 8 + grp) * RSH + pch];
            #pragma unroll
            for (int mt = 0; mt < 2; ++mt) {
                const int ar = m_base + mt * 16 + grp;
                const uint2 ua = *(const uint2*)&Ab[ar * RSH + pch];
                const uint2 ub = *(const uint2*)&Ab[(ar + 8) * RSH + pch];
                #pragma unroll
                for (int nt = 0; nt < 4; ++nt)
                    mma_f16(acc[mt][nt], ua.x, ub.x, ua.y, ub.y,
                            bf[nt].x, bf[nt].y);
            }
        }
        if (++buf == STAGES) buf = 0;

        asm volatile("cp.async.wait_group 1;");
        __syncthreads();
    }

    #pragma unroll
    for (int mt = 0; mt < 2; ++mt) {
        const int mrow = m0 + m_base + mt * 16 + grp;
        #pragma unroll
        for (int nt = 0; nt < 4; ++nt) {
            const int fc = f0 + n_base + nt * 8 + 2 * tig;
            const float b0v = bias[fc], b1v = bias[fc + 1];
            float2 r0 = make_float2(acc[mt][nt][0] + b0v, acc[mt][nt][1] + b1v);
            float2 r1 = make_float2(acc[mt][nt][2] + b0v, acc[mt][nt][3] + b1v);
            *(float2*)&Y[(size_t)mrow * FF + fc] = r0;
            *(float2*)&Y[(size_t)(mrow + 8) * FF + fc] = r1;
        }
    }
}

// ---------------------------------------------------------------------------
__device__ __forceinline__ float2 row_reduce2(float s, float q, float* sh8)
{
    __syncthreads();
    const int lane = threadIdx.x & 31;
    const int w    = threadIdx.x >> 5;
    #pragma unroll
    for (int o = 16; o > 0; o >>= 1) {
        s += __shfl_down_sync(0xffffffffu, s, o);
        q += __shfl_down_sync(0xffffffffu, q, o);
    }
    if (lane == 0) { sh8[w] = s; sh8[4 + w] = q; }
    __syncthreads();
    if (threadIdx.x == 0) {
        sh8[0] = sh8[0] + sh8[1] + sh8[2] + sh8[3];
        sh8[4] = sh8[4] + sh8[5] + sh8[6] + sh8[7];
    }
    __syncthreads();
    return make_float2(sh8[0], sh8[4]);
}

// LN+ReLU -> fp16 permuted; 4 rows per block, 128 thr per row.
__global__ __launch_bounds__(512) void ln_relu_kernel(
    const float* __restrict__ In, const float* __restrict__ gam,
    const float* __restrict__ bet, __half* __restrict__ Out)
{
    __shared__ float sh[4][8];
    const int row = blockIdx.x * 4 + threadIdx.y;
    const int t   = threadIdx.x;
    const float* p = In + (size_t)row * FF;
    float v0 = p[t], v1 = p[t + 128], v2 = p[t + 256];
    float2 r = row_reduce2(v0 + v1 + v2, v0 * v0 + v1 * v1 + v2 * v2,
                           sh[threadIdx.y]);
    const float mu  = r.x * (1.0f / FF);
    const float var = r.y * (1.0f / FF) - mu * mu;
    const float rs  = rsqrtf(var + LN_EPS);
    __half* o = Out + (size_t)row * FF;
    float v[3] = {v0, v1, v2};
    #pragma unroll
    for (int i = 0; i < 3; i++) {
        const int f = t + i * 128;
        const float h = fmaxf((v[i] - mu) * rs * gam[f] + bet[f], 0.0f);
        const int blk = f >> 4, j = f & 15;
        o[(blk << 4) + perm16h(j)] = __float2half_rn(h);
    }
}

__global__ __launch_bounds__(512) void ln_linear_kernel(
    const float* __restrict__ In, const float* __restrict__ gam,
    const float* __restrict__ bet, const float* __restrict__ lw,
    const float* __restrict__ lb, float* __restrict__ dur)
{
    __shared__ float sh[4][8];
    const int row = blockIdx.x * 4 + threadIdx.y;
    const int t   = threadIdx.x;
    const float* p = In + (size_t)row * FF;
    float v0 = p[t], v1 = p[t + 128], v2 = p[t + 256];
    float2 r = row_reduce2(v0 + v1 + v2, v0 * v0 + v1 * v1 + v2 * v2,
                           sh[threadIdx.y]);
    const float mu  = r.x * (1.0f / FF);
    const float var = r.y * (1.0f / FF) - mu * mu;
    const float rs  = rsqrtf(var + LN_EPS);
    float v[3] = {v0, v1, v2};
    float acc = 0.0f;
    #pragma unroll
    for (int i = 0; i < 3; i++) {
        const int f = t + i * 128;
        float h = fmaxf((v[i] - mu) * rs * gam[f] + bet[f], 0.0f);
        acc += h * lw[f];
    }
    float2 r2 = row_reduce2(acc, 0.0f, sh[threadIdx.y]);
    if (t == 0) dur[row] = fmaxf(r2.x + lb[0], 0.0f);
}

// ---------------------------------------------------------------------------
extern "C" void kernel_launch(void* const* d_in, const int* in_sizes, int n_in,
                              void* d_out, int out_size)
{
    const float* x     = (const float*)d_in[0];
    const float* c1_w  = (const float*)d_in[1];
    const float* c1_b  = (const float*)d_in[2];
    const float* ln1_g = (const float*)d_in[3];
    const float* ln1_b = (const float*)d_in[4];
    const float* c2_w  = (const float*)d_in[5];
    const float* c2_b  = (const float*)d_in[6];
    const float* ln2_g = (const float*)d_in[7];
    const float* ln2_b = (const float*)d_in[8];
    const float* lin_w = (const float*)d_in[9];
    const float* lin_b = (const float*)d_in[10];
    const int*   target= (const int*)d_in[11];

    const int M = (out_size - BB * LQ) / (BB * DD);

    float*  buf1;  cudaGetSymbolAddress((void**)&buf1,  g_buf1);
    __half* buf2h; cudaGetSymbolAddress((void**)&buf2h, g_buf2h);
    __half* xph;   cudaGetSymbolAddress((void**)&xph,   g_xph);
    __half* w1rh;  cudaGetSymbolAddress((void**)&w1rh,  g_w1rh);
    __half* w2rh;  cudaGetSymbolAddress((void**)&w2rh,  g_w2rh);

    float* out_expand = (float*)d_out;
    float* out_dur    = (float*)d_out + (size_t)BB * M * DD;

    const int smem_bytes = STAGES * (64 + 64) * RSH * 2;  // 36864
    cudaFuncSetAttribute(conv_expand_kernel,
                         cudaFuncAttributeMaxDynamicSharedMemorySize, smem_bytes);

    const int nfi       = BB * (M >> 8);
    const int exp_total = BB * (M >> 3);
    const int exp_half  = exp_total / 2;

    prep_all_kernel<<<NPX8 + NWR + nfi, 256>>>(x, xph, c1_w, w1rh, c2_w, w2rh,
                                               target, M);
    conv_expand_kernel<<<GEMM_BLOCKS + exp_half, 128, smem_bytes>>>(
        xph, w1rh, c1_b, buf1, x, out_expand, M, 0);
    ln_relu_kernel<<<MROWS / 4, dim3(128, 4)>>>(buf1, ln1_g, ln1_b, buf2h);
    conv_expand_kernel<<<GEMM_BLOCKS + (exp_total - exp_half), 128, smem_bytes>>>(
        buf2h, w2rh, c2_b, buf1, x, out_expand, M, exp_half);
    ln_linear_kernel<<<MROWS / 4, dim3(128, 4)>>>(buf1, ln2_g, ln2_b, lin_w, lin_b, out_dur);
}

// round 17
// speedup vs baseline: 1.2697x; 1.0228x over previous
#include <cuda_runtime.h>
#include <cuda_fp16.h>
#include <math.h>

#define BB   32
#define LQ   512
#define DD   384
#define FF   384
#define MROWS (BB*LQ)      // 16384
#define KDIM  (DD*3)       // 1152 halves
#define LN_EPS 1e-5f
#define STAGES 3
#define RSH 48             // smem row stride in halves (96 B)
#define GEMM_BLOCKS ((MROWS/64)*(FF/64))    // 1536
#define NPX8 (MROWS*DD/8/256)               // 3072
#define NWR (FF*2)                          // 768

// Scratch (no allocations allowed).
__device__ float  g_buf1[(size_t)MROWS * FF];
__device__ __half g_buf2h[(size_t)MROWS * FF];
__device__ __half g_xph [(size_t)MROWS * DD];
__device__ __half g_w1rh[(size_t)FF * KDIM];
__device__ __half g_w2rh[(size_t)FF * KDIM];
__device__ int    g_fidx[BB * 8192];        // frame -> source phoneme (-1 = pad)

// Half-pair permutation within each 16-half block.
__device__ __forceinline__ int perm16h(int j)
{
    const int p = j >> 1;
    const int pos = (p < 4) ? 2 * p : 2 * (p - 4) + 1;
    return pos * 2 + (j & 1);
}

// ---------------------------------------------------------------------------
// Fused prep: x fp32->fp16 (8 halves/thread) ; W reorder ; frame indices.
// ---------------------------------------------------------------------------
__global__ __launch_bounds__(256) void prep_all_kernel(
    const float* __restrict__ x, __half* __restrict__ xp,
    const float* __restrict__ W1, __half* __restrict__ Wr1,
    const float* __restrict__ W2, __half* __restrict__ Wr2,
    const int* __restrict__ target, int M)
{
    const int bidx = blockIdx.x;
    const int t = threadIdx.x;

    if (bidx < NPX8) {
        const int i   = bidx * 256 + t;
        const int b16 = i >> 1;
        const int h   = i & 1;
        const size_t sbase = (size_t)b16 * 16 + h * 8;
        const float4 v0 = *(const float4*)&x[sbase];
        const float4 v1 = *(const float4*)&x[sbase + 4];
        __half* d = xp + (size_t)b16 * 16 + (h ? 2 : 0);
        *(__half2*)&d[0]  = __floats2half2_rn(v0.x, v0.y);
        *(__half2*)&d[4]  = __floats2half2_rn(v0.z, v0.w);
        *(__half2*)&d[8]  = __floats2half2_rn(v1.x, v1.y);
        *(__half2*)&d[12] = __floats2half2_rn(v1.z, v1.w);
    } else if (bidx < NPX8 + NWR) {
        const int r2 = bidx - NPX8;
        const float* W  = (r2 >= FF) ? W2 : W1;
        __half*     Wr = (r2 >= FF) ? Wr2 : Wr1;
        const int f = (r2 >= FF) ? r2 - FF : r2;
        for (int i = t; i < KDIM; i += 256) {
            const int kseg = i / DD;
            const int r    = i - kseg * DD;
            const int blk  = r >> 4, j = r & 15;
            const int dst  = kseg * DD + (blk << 4) + perm16h(j);
            Wr[(size_t)f * KDIM + dst] =
                __float2half_rn(W[(size_t)f * KDIM + (blk * 16 + j) * 3 + kseg]);
        }
    } else {
        __shared__ int s[512];
        const int fb  = bidx - (NPX8 + NWR);
        const int bpB = M >> 8;
        const int b   = fb / bpB;
        const int fr0 = (fb - b * bpB) * 256;
        s[t]       = target[b * LQ + t];
        s[t + 256] = target[b * LQ + t + 256];
        __syncthreads();
        for (int off = 1; off < 512; off <<= 1) {
            const int v0 = (t >= off) ? s[t - off] : 0;
            const int v1 = s[t + 256 - off];
            __syncthreads();
            s[t] += v0;
            s[t + 256] += v1;
            __syncthreads();
        }
        const int fr = fr0 + t;
        const int total = s[511];
        int idx = -1;
        if (fr < total) {
            int lo = 0, hi = LQ;
            while (lo < hi) {
                const int mid = (lo + hi) >> 1;
                if (s[mid] <= fr) lo = mid + 1; else hi = mid;
            }
            idx = min(lo, LQ - 1);
        }
        g_fidx[b * M + fr] = idx;
    }
}

__device__ __forceinline__ void mma_f16(float c[4], unsigned a0, unsigned a1,
                                        unsigned a2, unsigned a3,
                                        unsigned b0, unsigned b1)
{
    asm volatile(
        "mma.sync.aligned.m16n8k16.row.col.f32.f16.f16.f32 "
        "{%0,%1,%2,%3}, {%4,%5,%6,%7}, {%8,%9}, {%0,%1,%2,%3};"
        : "+f"(c[0]), "+f"(c[1]), "+f"(c[2]), "+f"(c[3])
        : "r"(a0), "r"(a1), "r"(a2), "r"(a3), "r"(b0), "r"(b1));
}

__device__ __forceinline__ void cp16(unsigned dst, const void* src, bool p)
{
    const int sz = p ? 16 : 0;
    asm volatile("cp.async.cg.shared.global [%0], [%1], 16, %2;\n"
                 :: "r"(dst), "l"(src), "r"(sz));
}

// ---------------------------------------------------------------------------
// Conv fp16 mma (R12-proven): CTA 64x64, BK=32, 128 thr, 4 warps 2x2,
// 3-stage cp.async, 6 CTAs/SM, triple-unrolled loop (literal stage ids).
// Blocks >= GEMM_BLOCKS: expand, 16-frame groups via g_fidx.
// ---------------------------------------------------------------------------
__global__ __launch_bounds__(128, 6) void conv_expand_kernel(
    const __half* __restrict__ Asrc, const __half* __restrict__ Wr,
    const float* __restrict__ bias, float* __restrict__ Y,
    const float* __restrict__ X, float* __restrict__ out,
    int M, int exp_base)
{
    if (blockIdx.x >= GEMM_BLOCKS) {
        // ---------------- expand: 16 frames = 1536 float4 over 128 thr ------
        const int g   = blockIdx.x - GEMM_BLOCKS + exp_base;
        const int gpb = M >> 4;
        const int b   = g / gpb;
        const int fg  = g - b * gpb;
        const int* fi = g_fidx + b * M + fg * 16;
        float4* obase = (float4*)(out + (size_t)b * M * DD) + (size_t)fg * 1536;
        #pragma unroll
        for (int i = 0; i < 12; ++i) {
            const int idx  = i * 128 + threadIdx.x;    // 0..1535
            const int fr16 = idx / 96;
            const int lane = idx - fr16 * 96;
            const int sidx = __ldg(&fi[fr16]);
            if (sidx < 0) {
                __stcs(&obase[idx], make_float4(0.f, 0.f, 0.f, 0.f));
            } else {
                const float4* src = (const float4*)(X + ((size_t)b * LQ + sidx) * DD);
                __stcs(&obase[idx], __ldg(&src[lane]));
            }
        }
        return;
    }

    // ---------------- conv ----------------
    extern __shared__ __half smh[];
    __half* As = smh;                          // [STAGES][64][RSH]
    __half* Bs = smh + STAGES * 64 * RSH;      // [STAGES][64][RSH]

    const int f0 = (blockIdx.x % 6) * 64;
    const int m0 = (blockIdx.x / 6) * 64;
    const int t  = threadIdx.x;
    const int lane = t & 31, grp = lane >> 2, tig = lane & 3;
    const int warp = t >> 5;
    const int m_base = (warp & 1) * 32;
    const int n_base = (warp >> 1) * 32;

    const int lrow = t >> 2;
    const int c    = t & 3;

    int bA[2], lA[2];
    #pragma unroll
    for (int rr = 0; rr < 2; ++rr) {
        const int m = m0 + lrow + rr * 32;
        bA[rr] = m >> 9;
        lA[rr] = m & 511;
    }

    const unsigned aAd0 = (unsigned)__cvta_generic_to_shared(&As[lrow * RSH + c * 8]);
    const unsigned bAd0 = (unsigned)__cvta_generic_to_shared(&Bs[lrow * RSH + c * 8]);
    const unsigned STB   = 64 * RSH * 2;    // 6144
    const unsigned ROW32 = 32 * RSH * 2;    // 3072

    const __half* wr0 = Wr + (size_t)(f0 + lrow) * KDIM + c * 8;
    const __half* wr1 = Wr + (size_t)(f0 + lrow + 32) * KDIM + c * 8;

    float acc[2][4][4] = {};

    auto load_tile = [&](int it, int st) {
        const int kk0  = it * 32;
        const int kseg = (kk0 >= 384) + (kk0 >= 768);
        const int off  = kk0 - kseg * DD + c * 8;
        #pragma unroll
        for (int rr = 0; rr < 2; ++rr) {
            const int l2 = lA[rr] + kseg - 1;
            const bool v = (l2 >= 0) & (l2 < LQ);
            const __half* sa = Asrc + ((size_t)(bA[rr] << 9) + (v ? l2 : 0)) * DD + off;
            cp16(aAd0 + st * STB + rr * ROW32, sa, v);
        }
        cp16(bAd0 + st * STB,         wr0 + kk0, true);
        cp16(bAd0 + st * STB + ROW32, wr1 + kk0, true);
    };

    auto compute = [&](int bufc) {
        const __half* Ab = As + bufc * 64 * RSH;
        const __half* Bb = Bs + bufc * 64 * RSH;
        #pragma unroll
        for (int ks = 0; ks < 2; ++ks) {
            const int pch = ks * 16 + tig * 4;
            uint2 bf[4];
            #pragma unroll
            for (int nt = 0; nt < 4; ++nt)
                bf[nt] = *(const uint2*)&Bb[(n_base + nt * 8 + grp) * RSH + pch];
            #pragma unroll
            for (int mt = 0; mt < 2; ++mt) {
                const int ar = m_base + mt * 16 + grp;
                const uint2 ua = *(const uint2*)&Ab[ar * RSH + pch];
                const uint2 ub = *(const uint2*)&Ab[(ar + 8) * RSH + pch];
                #pragma unroll
                for (int nt = 0; nt < 4; ++nt)
                    mma_f16(acc[mt][nt], ua.x, ub.x, ua.y, ub.y,
                            bf[nt].x, bf[nt].y);
            }
        }
    };

    load_tile(0, 0);
    asm volatile("cp.async.commit_group;");
    load_tile(1, 1);
    asm volatile("cp.async.commit_group;");
    asm volatile("cp.async.wait_group 1;");
    __syncthreads();

    const int NIT = KDIM / 32;   // 36 = 12 triples
    #pragma unroll 1
    for (int it0 = 0; it0 < NIT; it0 += 3) {
        // body 0: compute buf 0, prefetch into stage 2
        if (it0 + 2 < NIT) load_tile(it0 + 2, 2);
        asm volatile("cp.async.commit_group;");
        compute(0);
        asm volatile("cp.async.wait_group 1;");
        __syncthreads();
        // body 1: compute buf 1, prefetch into stage 0
        if (it0 + 3 < NIT) load_tile(it0 + 3, 0);
        asm volatile("cp.async.commit_group;");
        compute(1);
        asm volatile("cp.async.wait_group 1;");
        __syncthreads();
        // body 2: compute buf 2, prefetch into stage 1
        if (it0 + 4 < NIT) load_tile(it0 + 4, 1);
        asm volatile("cp.async.commit_group;");
        compute(2);
        asm volatile("cp.async.wait_group 1;");
        __syncthreads();
    }

    #pragma unroll
    for (int mt = 0; mt < 2; ++mt) {
        const int mrow = m0 + m_base + mt * 16 + grp;
        #pragma unroll
        for (int nt = 0; nt < 4; ++nt) {
            const int fc = f0 + n_base + nt * 8 + 2 * tig;
            const float b0v = __ldg(&bias[fc]), b1v = __ldg(&bias[fc + 1]);
            float2 r0 = make_float2(acc[mt][nt][0] + b0v, acc[mt][nt][1] + b1v);
            float2 r1 = make_float2(acc[mt][nt][2] + b0v, acc[mt][nt][3] + b1v);
            *(float2*)&Y[(size_t)mrow * FF + fc] = r0;
            *(float2*)&Y[(size_t)(mrow + 8) * FF + fc] = r1;
        }
    }
}

// ---------------------------------------------------------------------------
__device__ __forceinline__ float2 row_reduce2(float s, float q, float* sh8)
{
    __syncthreads();
    const int lane = threadIdx.x & 31;
    const int w    = threadIdx.x >> 5;
    #pragma unroll
    for (int o = 16; o > 0; o >>= 1) {
        s += __shfl_down_sync(0xffffffffu, s, o);
        q += __shfl_down_sync(0xffffffffu, q, o);
    }
    if (lane == 0) { sh8[w] = s; sh8[4 + w] = q; }
    __syncthreads();
    if (threadIdx.x == 0) {
        sh8[0] = sh8[0] + sh8[1] + sh8[2] + sh8[3];
        sh8[4] = sh8[4] + sh8[5] + sh8[6] + sh8[7];
    }
    __syncthreads();
    return make_float2(sh8[0], sh8[4]);
}

// LN+ReLU -> fp16 permuted; 4 rows per block, 128 thr per row.
__global__ __launch_bounds__(512) void ln_relu_kernel(
    const float* __restrict__ In, const float* __restrict__ gam,
    const float* __restrict__ bet, __half* __restrict__ Out)
{
    __shared__ float sh[4][8];
    const int row = blockIdx.x * 4 + threadIdx.y;
    const int t   = threadIdx.x;
    const float* p = In + (size_t)row * FF;
    float v0 = p[t], v1 = p[t + 128], v2 = p[t + 256];
    float2 r = row_reduce2(v0 + v1 + v2, v0 * v0 + v1 * v1 + v2 * v2,
                           sh[threadIdx.y]);
    const float mu  = r.x * (1.0f / FF);
    const float var = r.y * (1.0f / FF) - mu * mu;
    const float rs  = rsqrtf(var + LN_EPS);
    __half* o = Out + (size_t)row * FF;
    float v[3] = {v0, v1, v2};
    #pragma unroll
    for (int i = 0; i < 3; i++) {
        const int f = t + i * 128;
        const float h = fmaxf((v[i] - mu) * rs * gam[f] + bet[f], 0.0f);
        const int blk = f >> 4, j = f & 15;
        o[(blk << 4) + perm16h(j)] = __float2half_rn(h);
    }
}

__global__ __launch_bounds__(512) void ln_linear_kernel(
    const float* __restrict__ In, const float* __restrict__ gam,
    const float* __restrict__ bet, const float* __restrict__ lw,
    const float* __restrict__ lb, float* __restrict__ dur)
{
    __shared__ float sh[4][8];
    const int row = blockIdx.x * 4 + threadIdx.y;
    const int t   = threadIdx.x;
    const float* p = In + (size_t)row * FF;
    float v0 = p[t], v1 = p[t + 128], v2 = p[t + 256];
    float2 r = row_reduce2(v0 + v1 + v2, v0 * v0 + v1 * v1 + v2 * v2,
                           sh[threadIdx.y]);
    const float mu  = r.x * (1.0f / FF);
    const float var = r.y * (1.0f / FF) - mu * mu;
    const float rs  = rsqrtf(var + LN_EPS);
    float v[3] = {v0, v1, v2};
    float acc = 0.0f;
    #pragma unroll
    for (int i = 0; i < 3; i++) {
        const int f = t + i * 128;
        float h = fmaxf((v[i] - mu) * rs * gam[f] + bet[f], 0.0f);
        acc += h * lw[f];
    }
    float2 r2 = row_reduce2(acc, 0.0f, sh[threadIdx.y]);
    if (t == 0) dur[row] = fmaxf(r2.x + lb[0], 0.0f);
}

// ---------------------------------------------------------------------------
extern "C" void kernel_launch(void* const* d_in, const int* in_sizes, int n_in,
                              void* d_out, int out_size)
{
    const float* x     = (const float*)d_in[0];
    const float* c1_w  = (const float*)d_in[1];
    const float* c1_b  = (const float*)d_in[2];
    const float* ln1_g = (const float*)d_in[3];
    const float* ln1_b = (const float*)d_in[4];
    const float* c2_w  = (const float*)d_in[5];
    const float* c2_b  = (const float*)d_in[6];
    const float* ln2_g = (const float*)d_in[7];
    const float* ln2_b = (const float*)d_in[8];
    const float* lin_w = (const float*)d_in[9];
    const float* lin_b = (const float*)d_in[10];
    const int*   target= (const int*)d_in[11];

    const int M = (out_size - BB * LQ) / (BB * DD);

    float*  buf1;  cudaGetSymbolAddress((void**)&buf1,  g_buf1);
    __half* buf2h; cudaGetSymbolAddress((void**)&buf2h, g_buf2h);
    __half* xph;   cudaGetSymbolAddress((void**)&xph,   g_xph);
    __half* w1rh;  cudaGetSymbolAddress((void**)&w1rh,  g_w1rh);
    __half* w2rh;  cudaGetSymbolAddress((void**)&w2rh,  g_w2rh);

    float* out_expand = (float*)d_out;
    float* out_dur    = (float*)d_out + (size_t)BB * M * DD;

    const int smem_bytes = STAGES * (64 + 64) * RSH * 2;  // 36864
    cudaFuncSetAttribute(conv_expand_kernel,
                         cudaFuncAttributeMaxDynamicSharedMemorySize, smem_bytes);

    const int nfi       = BB * (M >> 8);
    const int exp_total = BB * (M >> 4);   // 8192 (16-frame groups)
    const int exp_half  = exp_total / 2;

    prep_all_kernel<<<NPX8 + NWR + nfi, 256>>>(x, xph, c1_w, w1rh, c2_w, w2rh,
                                               target, M);
    conv_expand_kernel<<<GEMM_BLOCKS + exp_half, 128, smem_bytes>>>(
        xph, w1rh, c1_b, buf1, x, out_expand, M, 0);
    ln_relu_kernel<<<MROWS / 4, dim3(128, 4)>>>(buf1, ln1_g, ln1_b, buf2h);
    conv_expand_kernel<<<GEMM_BLOCKS + (exp_total - exp_half), 128, smem_bytes>>>(
        buf2h, w2rh, c2_b, buf1, x, out_expand, M, exp_half);
    ln_linear_kernel<<<MROWS / 4, dim3(128, 4)>>>(buf1, ln2_g, ln2_b, lin_w, lin_b, out_dur);
}